// round 11
// baseline (speedup 1.0000x reference)
#include <cuda_runtime.h>
#include <cuda_bf16.h>

// Problem constants
#define NK 3
#define NB 8
#define NT 1024
#define ND 1024
#define NR 32
#define ROWS_K (NB * NT)          // 8192 rows per area
#define ROWS_ALL (NK * ROWS_K)    // 24576 rows total
#define YN ((size_t)ROWS_ALL * ND) // output elems for y

// ---------------- scratch (device globals; no allocation allowed) -------------
__device__ float g_amp[24 * 8 * 1024];
__device__ float g_am[24 * 1024];
__device__ float g_pm[NB * NK * ND];
__device__ float g_h0[NB * NK * ND];
__device__ float g_h1[NB * 2 * ND];
__device__ float g_alpha[NB * NK];
__device__ float g_low[(size_t)ROWS_ALL * NR];

// packed bf16 hi/lo planes (u32 = pair of adjacent elements along k/d)
__device__ unsigned g_XH[(size_t)ROWS_ALL * 512];
__device__ unsigned g_XL[(size_t)ROWS_ALL * 512];
__device__ unsigned g_rH[(size_t)ROWS_K * 512];
__device__ unsigned g_rL[(size_t)ROWS_K * 512];
__device__ unsigned g_bcH[(size_t)ROWS_ALL * 512];
__device__ unsigned g_bcL[(size_t)ROWS_ALL * 512];
__device__ unsigned g_ahH[(size_t)ROWS_ALL * 512];
__device__ unsigned g_ahL[(size_t)ROWS_ALL * 512];
// weights packed per k-pair: [kp][1024]
__device__ unsigned g_WbH[1536 * 1024], g_WbL[1536 * 1024];
__device__ unsigned g_WaH[1536 * 1024], g_WaL[1536 * 1024];
__device__ unsigned g_Wm1H[1536 * 1024], g_Wm1L[1536 * 1024];
__device__ unsigned g_Wm2H[1536 * 1024], g_Wm2L[1536 * 1024];
__device__ unsigned g_WgH[3072 * 1024], g_WgL[3072 * 1024];

__device__ float g_gate[(size_t)ROWS_ALL * ND];
__device__ float g_m[(size_t)ROWS_ALL * ND];

// ---------------- helpers -----------------------------------------------------
__device__ __forceinline__ float gelu_f(float x) {
    return 0.5f * x * (1.0f + erff(x * 0.7071067811865476f));
}
__device__ __forceinline__ float sigm_f(float x) {
    return 1.0f / (1.0f + expf(-x));
}

__device__ __forceinline__ void split2(float x, float y, unsigned &hi, unsigned &lo) {
    __nv_bfloat16 hx = __float2bfloat16_rn(x);
    __nv_bfloat16 hy = __float2bfloat16_rn(y);
    float rx = x - __bfloat162float(hx);
    float ry = y - __bfloat162float(hy);
    __nv_bfloat16 lx = __float2bfloat16_rn(rx);
    __nv_bfloat16 ly = __float2bfloat16_rn(ry);
    hi = (unsigned)__bfloat16_as_ushort(hx) | ((unsigned)__bfloat16_as_ushort(hy) << 16);
    lo = (unsigned)__bfloat16_as_ushort(lx) | ((unsigned)__bfloat16_as_ushort(ly) << 16);
}

__device__ __forceinline__ float2 join2(unsigned h, unsigned l) {
    float x = __bfloat162float(__ushort_as_bfloat16((unsigned short)(h & 0xffff)))
            + __bfloat162float(__ushort_as_bfloat16((unsigned short)(l & 0xffff)));
    float y = __bfloat162float(__ushort_as_bfloat16((unsigned short)(h >> 16)))
            + __bfloat162float(__ushort_as_bfloat16((unsigned short)(l >> 16)));
    return make_float2(x, y);
}

__device__ __forceinline__ void mma16816(float* c, const unsigned* a, unsigned b0, unsigned b1) {
    asm volatile(
        "mma.sync.aligned.m16n8k16.row.col.f32.bf16.bf16.f32 "
        "{%0,%1,%2,%3}, {%4,%5,%6,%7}, {%8,%9}, {%0,%1,%2,%3};"
        : "+f"(c[0]), "+f"(c[1]), "+f"(c[2]), "+f"(c[3])
        : "r"(a[0]), "r"(a[1]), "r"(a[2]), "r"(a[3]), "r"(b0), "r"(b1));
}

__device__ __forceinline__ void ldsm_x4(unsigned &r0, unsigned &r1, unsigned &r2, unsigned &r3,
                                        unsigned saddr) {
    asm volatile("ldmatrix.sync.aligned.m8n8.x4.shared.b16 {%0,%1,%2,%3}, [%4];"
                 : "=r"(r0), "=r"(r1), "=r"(r2), "=r"(r3) : "r"(saddr));
}

#define CP16(dst, src) asm volatile("cp.async.ca.shared.global [%0], [%1], 16;" :: "r"(dst), "l"(src) : "memory")
#define CP_COMMIT() asm volatile("cp.async.commit_group;" ::: "memory")
#define CP_WAIT0() asm volatile("cp.async.wait_group 0;" ::: "memory")

__device__ __forceinline__ float2 blockReduce2(float a, float b) {
    __shared__ float sa[8], sb[8];
    int lane = threadIdx.x & 31;
    int w = threadIdx.x >> 5;
#pragma unroll
    for (int o = 16; o > 0; o >>= 1) {
        a += __shfl_xor_sync(0xffffffffu, a, o);
        b += __shfl_xor_sync(0xffffffffu, b, o);
    }
    if (lane == 0) { sa[w] = a; sb[w] = b; }
    __syncthreads();
    if (w == 0) {
        a = (lane < 8) ? sa[lane] : 0.f;
        b = (lane < 8) ? sb[lane] : 0.f;
#pragma unroll
        for (int o = 4; o > 0; o >>= 1) {
            a += __shfl_xor_sync(0xffffffffu, a, o);
            b += __shfl_xor_sync(0xffffffffu, b, o);
        }
        if (lane == 0) { sa[0] = a; sb[0] = b; }
    }
    __syncthreads();
    return make_float2(sa[0], sb[0]);
}

// ---------------- pre-split kernels -------------------------------------------
__global__ void __launch_bounds__(256) kSplitX(const float* __restrict__ src,
                                               unsigned* __restrict__ hi,
                                               unsigned* __restrict__ lo) {
    size_t q = (size_t)blockIdx.x * 256 + threadIdx.x;
    float4 v = *(const float4*)(src + q * 4);
    unsigned h0, l0, h1, l1;
    split2(v.x, v.y, h0, l0);
    split2(v.z, v.w, h1, l1);
    *(uint2*)(hi + q * 2) = make_uint2(h0, h1);
    *(uint2*)(lo + q * 2) = make_uint2(l0, l1);
}

__global__ void __launch_bounds__(256) kSplitW(const float* __restrict__ src,
                                               unsigned* __restrict__ hi,
                                               unsigned* __restrict__ lo) {
    size_t q = (size_t)blockIdx.x * 256 + threadIdx.x;
    size_t kp = q >> 8;
    size_t n4 = (q & 255) * 4;
    float4 e = *(const float4*)(src + (kp * 2) * 1024 + n4);
    float4 o = *(const float4*)(src + (kp * 2 + 1) * 1024 + n4);
    unsigned h[4], l[4];
    split2(e.x, o.x, h[0], l[0]);
    split2(e.y, o.y, h[1], l[1]);
    split2(e.z, o.z, h[2], l[2]);
    split2(e.w, o.w, h[3], l[3]);
    *(uint4*)(hi + kp * 1024 + n4) = make_uint4(h[0], h[1], h[2], h[3]);
    *(uint4*)(lo + kp * 1024 + n4) = make_uint4(l[0], l[1], l[2], l[3]);
}

// ---------------- controller --------------------------------------------------
__global__ void __launch_bounds__(256) kMeans(const float* __restrict__ X) {
    int slab = blockIdx.x;
    int chunk = blockIdx.y;
    size_t base = (size_t)slab * (NT * ND) + (size_t)chunk * 128 * ND;
    int col = threadIdx.x * 4;
    float4 acc = make_float4(0.f, 0.f, 0.f, 0.f);
#pragma unroll 4
    for (int t = 0; t < 128; t++) {
        float4 v = *(const float4*)(X + base + (size_t)t * ND + col);
        acc.x += v.x; acc.y += v.y; acc.z += v.z; acc.w += v.w;
    }
    *(float4*)&g_amp[(size_t)slab * 8192 + (size_t)chunk * 1024 + col] = acc;
}

__global__ void __launch_bounds__(256) kAm() {
    int bid = blockIdx.x;
    int b = bid / 3, k = bid % 3;
    int slab = k * 8 + b;
    for (int i = threadIdx.x; i < 1024; i += 256) {
        float acc = 0.f;
#pragma unroll
        for (int c = 0; c < 8; c++) acc += g_amp[(size_t)slab * 8192 + c * 1024 + i];
        g_am[bid * 1024 + i] = acc * (1.0f / 1024.0f);
    }
}

__global__ void __launch_bounds__(256) kPm2(const float* __restrict__ W,
                                            const float* __restrict__ bvec) {
    int col = blockIdx.x * 64 + (threadIdx.x & 63);
    int rg = threadIdx.x >> 6;
    float acc[6];
#pragma unroll
    for (int j = 0; j < 6; j++) acc[j] = 0.f;
    for (int dd = 0; dd < 1024; dd++) {
        float w = W[(size_t)dd * 1024 + col];
#pragma unroll
        for (int j = 0; j < 6; j++)
            acc[j] += g_am[(rg * 6 + j) * 1024 + dd] * w;
    }
    float bias = bvec[col];
#pragma unroll
    for (int j = 0; j < 6; j++)
        g_pm[(size_t)(rg * 6 + j) * 1024 + col] = gelu_f(acc[j] + bias);
}

__global__ void __launch_bounds__(256) kLN1(const float* __restrict__ gvec,
                                            const float* __restrict__ bvec) {
    int b = blockIdx.x;
    size_t base = (size_t)b * 3072;
    int i0 = threadIdx.x * 4;
    float4 v[3];
    float s = 0.f, sq = 0.f;
#pragma unroll
    for (int c = 0; c < 3; c++) {
        v[c] = *(const float4*)&g_pm[base + c * 1024 + i0];
        s += v[c].x + v[c].y + v[c].z + v[c].w;
        sq += v[c].x * v[c].x + v[c].y * v[c].y + v[c].z * v[c].z + v[c].w * v[c].w;
    }
    float2 r = blockReduce2(s, sq);
    float mu = r.x * (1.0f / 3072.0f);
    float var = r.y * (1.0f / 3072.0f) - mu * mu;
    float rstd = rsqrtf(var + 1e-5f);
#pragma unroll
    for (int c = 0; c < 3; c++) {
        int idx = c * 1024 + i0;
        float4 G = *(const float4*)(gvec + idx);
        float4 Bv = *(const float4*)(bvec + idx);
        float4 o;
        o.x = (v[c].x - mu) * rstd * G.x + Bv.x;
        o.y = (v[c].y - mu) * rstd * G.y + Bv.y;
        o.z = (v[c].z - mu) * rstd * G.z + Bv.z;
        o.w = (v[c].w - mu) * rstd * G.w + Bv.w;
        *(float4*)&g_h0[base + idx] = o;
    }
}

__global__ void __launch_bounds__(256) kH1(const float* __restrict__ W1,
                                           const float* __restrict__ b1) {
    int col = blockIdx.x * 64 + (threadIdx.x & 63);
    int bq = threadIdx.x >> 6;
    float a0 = 0.f, a1 = 0.f;
    const float* h0a = g_h0 + (size_t)bq * 3072;
    const float* h0b = g_h0 + (size_t)(bq + 4) * 3072;
    for (int dd = 0; dd < 3072; dd++) {
        float w = W1[(size_t)dd * 2048 + col];
        a0 += h0a[dd] * w;
        a1 += h0b[dd] * w;
    }
    float bias = b1[col];
    g_h1[(size_t)bq * 2048 + col] = gelu_f(a0 + bias);
    g_h1[(size_t)(bq + 4) * 2048 + col] = gelu_f(a1 + bias);
}

__global__ void __launch_bounds__(256) kLogits(const float* __restrict__ W2,
                                               const float* __restrict__ b2,
                                               const float* __restrict__ gum,
                                               float* __restrict__ outLog) {
    __shared__ float s0[256], s1[256], s2[256];
    int b = blockIdx.x;
    int tid = threadIdx.x;
    float a0 = 0.f, a1 = 0.f, a2 = 0.f;
    for (int dd = tid; dd < 2048; dd += 256) {
        float v = g_h1[(size_t)b * 2048 + dd];
        a0 += v * W2[dd * 3 + 0];
        a1 += v * W2[dd * 3 + 1];
        a2 += v * W2[dd * 3 + 2];
    }
    s0[tid] = a0; s1[tid] = a1; s2[tid] = a2;
    __syncthreads();
    for (int off = 128; off > 0; off >>= 1) {
        if (tid < off) { s0[tid] += s0[tid + off]; s1[tid] += s1[tid + off]; s2[tid] += s2[tid + off]; }
        __syncthreads();
    }
    if (tid == 0) {
        float lg[3];
        lg[0] = s0[0] + b2[0]; lg[1] = s1[0] + b2[1]; lg[2] = s2[0] + b2[2];
        float z[3];
#pragma unroll
        for (int j = 0; j < 3; j++) {
            outLog[b * 3 + j] = lg[j];
            z[j] = (lg[j] + gum[b * 3 + j]) * 1.25f;
        }
        float m = fmaxf(z[0], fmaxf(z[1], z[2]));
        float e0 = expf(z[0] - m), e1 = expf(z[1] - m), e2 = expf(z[2] - m);
        float inv = 1.0f / (e0 + e1 + e2);
        g_alpha[b * 3 + 0] = e0 * inv;
        g_alpha[b * 3 + 1] = e1 * inv;
        g_alpha[b * 3 + 2] = e2 * inv;
    }
}

// ---------------- router ------------------------------------------------------
__global__ void __launch_bounds__(256) kLow(const float* __restrict__ X,
                                            const float* __restrict__ V) {
    __shared__ float Xs[64][33];
    __shared__ float Vs[32][32];
    int row0 = blockIdx.x * 64;
    int k = row0 >> 13;
    int tid = threadIdx.x;
    int tx = tid & 31, ty = tid >> 5;
    float acc[8];
#pragma unroll
    for (int i = 0; i < 8; i++) acc[i] = 0.f;

    for (int d0 = 0; d0 < 1024; d0 += 32) {
#pragma unroll
        for (int i = 0; i < 8; i++) {
            int idx = tid + i * 256;
            int r = idx >> 5, c = idx & 31;
            Xs[r][c] = X[(size_t)(row0 + r) * ND + d0 + c];
        }
#pragma unroll
        for (int i = 0; i < 4; i++) {
            int idx = tid + i * 256;
            int dd = idx >> 5, rr = idx & 31;
            Vs[dd][rr] = V[((size_t)k * 1024 + d0 + dd) * 32 + rr];
        }
        __syncthreads();
#pragma unroll
        for (int dd = 0; dd < 32; dd++) {
            float vv = Vs[dd][tx];
#pragma unroll
            for (int rr = 0; rr < 8; rr++) acc[rr] += Xs[rr * 8 + ty][dd] * vv;
        }
        __syncthreads();
    }
#pragma unroll
    for (int rr = 0; rr < 8; rr++)
        g_low[(size_t)(row0 + rr * 8 + ty) * 32 + tx] = acc[rr];
}

__global__ void __launch_bounds__(256) kRouted(const float* __restrict__ U) {
    __shared__ float As[96][64];
    __shared__ float Us[96][64];
    int col0 = blockIdx.x * 64;
    int row0 = blockIdx.y * 64;
    int tid = threadIdx.x;
    int tx = tid & 15, ty = tid >> 4;

    for (int idx = tid; idx < 6144; idx += 256) {
        int r0 = idx / 96, p = idx - r0 * 96;
        int k = p >> 5, rr = p & 31;
        int row = row0 + r0;
        int b = row >> 10;
        As[p][r0] = g_alpha[b * 3 + k] * g_low[((size_t)k * 8192 + row) * 32 + rr];
    }
    for (int idx = tid; idx < 6144; idx += 256) {
        int p = idx >> 6, e = idx & 63;
        int k = p >> 5, rr = p & 31;
        Us[p][e] = U[((size_t)k * 1024 + col0 + e) * 32 + rr];
    }
    __syncthreads();

    float acc[4][4];
#pragma unroll
    for (int i = 0; i < 4; i++)
#pragma unroll
        for (int j = 0; j < 4; j++) acc[i][j] = 0.f;

#pragma unroll 8
    for (int p = 0; p < 96; p++) {
        float4 u4 = *(const float4*)&Us[p][tx * 4];
        float a0 = As[p][ty * 4 + 0], a1 = As[p][ty * 4 + 1];
        float a2 = As[p][ty * 4 + 2], a3 = As[p][ty * 4 + 3];
        acc[0][0] += a0 * u4.x; acc[0][1] += a0 * u4.y; acc[0][2] += a0 * u4.z; acc[0][3] += a0 * u4.w;
        acc[1][0] += a1 * u4.x; acc[1][1] += a1 * u4.y; acc[1][2] += a1 * u4.z; acc[1][3] += a1 * u4.w;
        acc[2][0] += a2 * u4.x; acc[2][1] += a2 * u4.y; acc[2][2] += a2 * u4.z; acc[2][3] += a2 * u4.w;
        acc[3][0] += a3 * u4.x; acc[3][1] += a3 * u4.y; acc[3][2] += a3 * u4.z; acc[3][3] += a3 * u4.w;
    }
#pragma unroll
    for (int i = 0; i < 4; i++) {
        unsigned h0, l0, h1, l1;
        split2(acc[i][0], acc[i][1], h0, l0);
        split2(acc[i][2], acc[i][3], h1, l1);
        size_t base = (size_t)(row0 + ty * 4 + i) * 512 + ((col0 + tx * 4) >> 1);
        *(uint2*)&g_rH[base] = make_uint2(h0, h1);
        *(uint2*)&g_rL[base] = make_uint2(l0, l1);
    }
}

// ============ tensor-core GEMM: cp.async fills + ldmatrix A frags ==============
// mode: 0=store fp32, 1=gelu fp32, 2=sigmoid(prev+v+bias) fp32,
//       3=prev*gelu(v) fp32, 4=gelu -> packed hi/lo planes
// csel: 0=bcomp(packed), 1=ah(packed), 2=gate(fp32), 3=m(fp32)
__global__ void __launch_bounds__(256) gemm_tc(
    const unsigned* __restrict__ hiA, const unsigned* __restrict__ loA, size_t aZ,
    const unsigned* __restrict__ hiW, const unsigned* __restrict__ loW,
    size_t wOffKp, size_t wZKp,
    const float* __restrict__ bias, int csel, int mode)
{
    const int z = blockIdx.z;
    const int row0 = blockIdx.y * 128;
    const int col0 = blockIdx.x * 128;

    const unsigned* Ah_g = hiA + (size_t)z * aZ + (size_t)row0 * 512;
    const unsigned* Al_g = loA + (size_t)z * aZ + (size_t)row0 * 512;
    const size_t wBase = ((size_t)z * wZKp + wOffKp) * 1024 + col0;

    // A: row-major [row][12] (8 used kp + 4 pad -> ldmatrix conflict-free)
    __shared__ unsigned Ah[2][128][12], Al[2][128][12];
    __shared__ unsigned Bh[2][8][132], Bl[2][8][132];

    const int tid = threadIdx.x;
    const int lane = tid & 31;
    const int wid = tid >> 5;
    const int wm = wid & 1;
    const int wn = wid >> 1;
    const int qrow = lane >> 2;
    const int qk = lane & 3;

    // fill mapping
    const int fr = tid >> 1;            // A row 0..127
    const int fq = tid & 1;             // A 16B-chunk (kp 0-3 / 4-7)
    const int bkp = tid >> 5;           // B kp 0..7
    const int bn4 = (tid & 31) * 4;     // B n offset

    const unsigned sAh = (unsigned)__cvta_generic_to_shared(&Ah[0][0][0]);
    const unsigned sAl = (unsigned)__cvta_generic_to_shared(&Al[0][0][0]);
    const unsigned sBh = (unsigned)__cvta_generic_to_shared(&Bh[0][0][0]);
    const unsigned sBl = (unsigned)__cvta_generic_to_shared(&Bl[0][0][0]);
    const unsigned A_BUF = 128 * 12 * 4;   // bytes per A buffer
    const unsigned B_BUF = 8 * 132 * 4;

    const unsigned daOff = (unsigned)(fr * 48 + fq * 16);
    const unsigned dbOff = (unsigned)(bkp * 132 * 4 + bn4 * 4);

    float acc[4][4][4];
#pragma unroll
    for (int i = 0; i < 4; i++)
#pragma unroll
        for (int j = 0; j < 4; j++)
#pragma unroll
            for (int q = 0; q < 4; q++) acc[i][j][q] = 0.f;

    // prologue: issue stage 0 into buffer 0
    {
        const unsigned* ga = Ah_g + (size_t)fr * 512 + fq * 4;
        const unsigned* gal = Al_g + (size_t)fr * 512 + fq * 4;
        CP16(sAh + daOff, ga);
        CP16(sAl + daOff, gal);
        CP16(sBh + dbOff, &hiW[wBase + (size_t)bkp * 1024 + bn4]);
        CP16(sBl + dbOff, &loW[wBase + (size_t)bkp * 1024 + bn4]);
        CP_COMMIT();
    }

    // ldmatrix lane address components (A): row = mb + (lane&15), khalf = lane>>4
    const unsigned lrow = (unsigned)(lane & 15);
    const unsigned lkh = (unsigned)((lane >> 4) * 16);   // byte offset for k-half

#pragma unroll 1
    for (int kt = 0; kt < 64; kt++) {
        const int cur = kt & 1;
        CP_WAIT0();
        __syncthreads();

        // issue next stage into the other buffer (overlaps compute)
        if (kt < 63) {
            const int nb = cur ^ 1;
            size_t kpo = (size_t)(kt + 1) * 8;
            CP16(sAh + nb * A_BUF + daOff, Ah_g + (size_t)fr * 512 + kpo + fq * 4);
            CP16(sAl + nb * A_BUF + daOff, Al_g + (size_t)fr * 512 + kpo + fq * 4);
            CP16(sBh + nb * B_BUF + dbOff, &hiW[wBase + (kpo + bkp) * 1024 + bn4]);
            CP16(sBl + nb * B_BUF + dbOff, &loW[wBase + (kpo + bkp) * 1024 + bn4]);
            CP_COMMIT();
        }

        // B fragments
        unsigned fBh[4][2], fBl[4][2];
#pragma unroll
        for (int nt = 0; nt < 4; nt++) {
            int nbx = wn * 32 + nt * 8 + qrow;
            fBh[nt][0] = Bh[cur][qk][nbx]; fBh[nt][1] = Bh[cur][qk + 4][nbx];
            fBl[nt][0] = Bl[cur][qk][nbx]; fBl[nt][1] = Bl[cur][qk + 4][nbx];
        }

        // A fragments via ldmatrix + 12 mma per mt
#pragma unroll
        for (int mt = 0; mt < 4; mt++) {
            unsigned mb = (unsigned)(wm * 64 + mt * 16);
            unsigned rowAddr = (mb + lrow) * 48 + lkh;
            unsigned fAh[4], fAl[4];
            ldsm_x4(fAh[0], fAh[1], fAh[2], fAh[3], sAh + cur * A_BUF + rowAddr);
            ldsm_x4(fAl[0], fAl[1], fAl[2], fAl[3], sAl + cur * A_BUF + rowAddr);
#pragma unroll
            for (int nt = 0; nt < 4; nt++) {
                mma16816(acc[mt][nt], fAh, fBh[nt][0], fBh[nt][1]);
                mma16816(acc[mt][nt], fAh, fBl[nt][0], fBl[nt][1]);
                mma16816(acc[mt][nt], fAl, fBh[nt][0], fBh[nt][1]);
            }
        }
    }

    // ---------------- fused epilogue ----------------
    if (mode == 4) {
        unsigned* cH = (csel == 0 ? g_bcH : g_ahH) + ((size_t)z * ROWS_K + row0) * 512 + (col0 >> 1);
        unsigned* cL = (csel == 0 ? g_bcL : g_ahL) + ((size_t)z * ROWS_K + row0) * 512 + (col0 >> 1);
#pragma unroll
        for (int mt = 0; mt < 4; mt++) {
            int rbase = wm * 64 + mt * 16 + qrow;
#pragma unroll
            for (int half = 0; half < 2; half++) {
                int r = rbase + half * 8;
#pragma unroll
                for (int nt = 0; nt < 4; nt++) {
                    int c = wn * 32 + nt * 8 + 2 * qk;
                    float v0 = gelu_f(acc[mt][nt][half * 2 + 0]);
                    float v1 = gelu_f(acc[mt][nt][half * 2 + 1]);
                    unsigned h, l;
                    split2(v0, v1, h, l);
                    cH[(size_t)r * 512 + (c >> 1)] = h;
                    cL[(size_t)r * 512 + (c >> 1)] = l;
                }
            }
        }
    } else {
        float* Cb = (csel == 2 ? g_gate : g_m) + (size_t)z * ROWS_K * ND + (size_t)row0 * ND + col0;
#pragma unroll
        for (int mt = 0; mt < 4; mt++) {
            int rbase = wm * 64 + mt * 16 + qrow;
#pragma unroll
            for (int half = 0; half < 2; half++) {
                int r = rbase + half * 8;
#pragma unroll
                for (int nt = 0; nt < 4; nt++) {
                    int c = wn * 32 + nt * 8 + 2 * qk;
                    float v0 = acc[mt][nt][half * 2 + 0];
                    float v1 = acc[mt][nt][half * 2 + 1];
                    float* cp = Cb + (size_t)r * ND + c;
                    if (mode == 0) {
                        *(float2*)cp = make_float2(v0, v1);
                    } else if (mode == 1) {
                        *(float2*)cp = make_float2(gelu_f(v0), gelu_f(v1));
                    } else if (mode == 2) {
                        float2 p = *(float2*)cp;
                        float b0 = bias[(size_t)z * ND + col0 + c];
                        float b1 = bias[(size_t)z * ND + col0 + c + 1];
                        *(float2*)cp = make_float2(sigm_f(p.x + v0 + b0), sigm_f(p.y + v1 + b1));
                    } else {
                        float2 p = *(float2*)cp;
                        *(float2*)cp = make_float2(p.x * gelu_f(v0), p.y * gelu_f(v1));
                    }
                }
            }
        }
    }
}

// ---------------- final: y = LN(x + (1-g)*b + g*m) * lng + lnb ----------------
__global__ void __launch_bounds__(256) kFinal(const float* __restrict__ X,
                                              const float* __restrict__ cg,
                                              const float* __restrict__ cb,
                                              float* __restrict__ out) {
    size_t row = blockIdx.x;
    int k = (int)(row >> 13);
    size_t base = row * ND + threadIdx.x * 4;
    size_t pbase = row * 512 + threadIdx.x * 2;
    float4 x  = *(const float4*)(X + base);
    uint2 bh = *(const uint2*)(g_bcH + pbase);
    uint2 bl = *(const uint2*)(g_bcL + pbase);
    float2 b01 = join2(bh.x, bl.x);
    float2 b23 = join2(bh.y, bl.y);
    float4 gv = *(const float4*)(g_gate + base);
    float4 mv = *(const float4*)(g_m + base);
    float4 v;
    v.x = x.x + (1.f - gv.x) * b01.x + gv.x * mv.x;
    v.y = x.y + (1.f - gv.y) * b01.y + gv.y * mv.y;
    v.z = x.z + (1.f - gv.z) * b23.x + gv.z * mv.z;
    v.w = x.w + (1.f - gv.w) * b23.y + gv.w * mv.w;
    float s = v.x + v.y + v.z + v.w;
    float sq = v.x * v.x + v.y * v.y + v.z * v.z + v.w * v.w;
    float2 r = blockReduce2(s, sq);
    float mu = r.x * (1.0f / 1024.0f);
    float var = r.y * (1.0f / 1024.0f) - mu * mu;
    float rstd = rsqrtf(var + 1e-5f);
    int ci = k * 1024 + threadIdx.x * 4;
    float4 G = *(const float4*)(cg + ci);
    float4 Bv = *(const float4*)(cb + ci);
    float4 o;
    o.x = (v.x - mu) * rstd * G.x + Bv.x;
    o.y = (v.y - mu) * rstd * G.y + Bv.y;
    o.z = (v.z - mu) * rstd * G.z + Bv.z;
    o.w = (v.w - mu) * rstd * G.w + Bv.w;
    *(float4*)(out + base) = o;
}

// ---------------- launch ------------------------------------------------------
extern "C" void kernel_launch(void* const* d_in, const int* in_sizes, int n_in,
                              void* d_out, int out_size) {
    (void)in_sizes; (void)n_in; (void)out_size;
    const float* X    = (const float*)d_in[0];
    const float* gum  = (const float*)d_in[1];
    const float* prW  = (const float*)d_in[2];
    const float* prB  = (const float*)d_in[3];
    const float* hlg  = (const float*)d_in[4];
    const float* hlb  = (const float*)d_in[5];
    const float* W1   = (const float*)d_in[6];
    const float* b1   = (const float*)d_in[7];
    const float* W2   = (const float*)d_in[8];
    const float* b2   = (const float*)d_in[9];
    const float* U    = (const float*)d_in[10];
    const float* V    = (const float*)d_in[11];
    const float* Wb   = (const float*)d_in[12];
    const float* Wa   = (const float*)d_in[13];
    const float* Wg   = (const float*)d_in[14];
    const float* bg   = (const float*)d_in[15];
    const float* Wm1  = (const float*)d_in[16];
    const float* Wm2  = (const float*)d_in[17];
    const float* clg  = (const float*)d_in[18];
    const float* clb  = (const float*)d_in[19];
    float* out = (float*)d_out;

    unsigned *xh, *xl, *wbh, *wbl, *wah, *wal, *wgh, *wgl, *wm1h, *wm1l, *wm2h, *wm2l;
    unsigned *rh, *rl, *bch, *bcl, *ahh, *ahl;
    cudaGetSymbolAddress((void**)&xh, g_XH);   cudaGetSymbolAddress((void**)&xl, g_XL);
    cudaGetSymbolAddress((void**)&wbh, g_WbH); cudaGetSymbolAddress((void**)&wbl, g_WbL);
    cudaGetSymbolAddress((void**)&wah, g_WaH); cudaGetSymbolAddress((void**)&wal, g_WaL);
    cudaGetSymbolAddress((void**)&wgh, g_WgH); cudaGetSymbolAddress((void**)&wgl, g_WgL);
    cudaGetSymbolAddress((void**)&wm1h, g_Wm1H); cudaGetSymbolAddress((void**)&wm1l, g_Wm1L);
    cudaGetSymbolAddress((void**)&wm2h, g_Wm2H); cudaGetSymbolAddress((void**)&wm2l, g_Wm2L);
    cudaGetSymbolAddress((void**)&rh, g_rH);   cudaGetSymbolAddress((void**)&rl, g_rL);
    cudaGetSymbolAddress((void**)&bch, g_bcH); cudaGetSymbolAddress((void**)&bcl, g_bcL);
    cudaGetSymbolAddress((void**)&ahh, g_ahH); cudaGetSymbolAddress((void**)&ahl, g_ahL);

    const size_t AZ = (size_t)ROWS_K * 512;
    dim3 gg(8, 64, 3);

    // splits first; X-only GEMMs early (6th launch = gemm_tc for ncu capture)
    kSplitX<<<24576, 256>>>(X, xh, xl);
    kSplitW<<<1536, 256>>>(Wb, wbh, wbl);
    kSplitW<<<3072, 256>>>(Wg, wgh, wgl);
    kSplitW<<<1536, 256>>>(Wm1, wm1h, wm1l);
    kSplitW<<<1536, 256>>>(Wm2, wm2h, wm2l);
    gemm_tc<<<gg, 256>>>(xh, xl, AZ, wbh, wbl, 0, 512, nullptr, 0, 4);   // bcomp = gelu(X@Wb) -> packed
    gemm_tc<<<gg, 256>>>(xh, xl, AZ, wgh, wgl, 0, 1024, nullptr, 2, 0);  // gate = X@Wg_top (raw)
    kSplitW<<<1536, 256>>>(Wa, wah, wal);

    // controller
    kMeans<<<dim3(24, 8), 256>>>(X);
    kAm<<<24, 256>>>();
    kPm2<<<16, 256>>>(prW, prB);
    kLN1<<<8, 256>>>(hlg, hlb);
    kH1<<<32, 256>>>(W1, b1);
    kLogits<<<8, 256>>>(W2, b2, gum, out + YN);

    // router
    kLow<<<ROWS_ALL / 64, 256>>>(X, V);
    kRouted<<<dim3(16, 128), 256>>>(U);

    // routed-dependent + second pass GEMMs
    gemm_tc<<<gg, 256>>>(rh, rl, 0,  wah, wal, 0, 512, nullptr, 1, 4);    // ah = gelu(routed@Wa) -> packed
    gemm_tc<<<gg, 256>>>(rh, rl, 0,  wgh, wgl, 512, 1024, bg, 2, 2);      // gate = sigmoid(.+routed@Wg_bot+bg)
    gemm_tc<<<gg, 256>>>(bch, bcl, AZ, wm1h, wm1l, 0, 512, nullptr, 3, 1); // m = gelu(bcomp@Wm1)
    gemm_tc<<<gg, 256>>>(ahh, ahl, AZ, wm2h, wm2l, 0, 512, nullptr, 3, 3); // m *= gelu(ah@Wm2)

    // final LN + output
    kFinal<<<ROWS_ALL, 256>>>(X, clg, clb, out);
}

// round 14
// speedup vs baseline: 1.3982x; 1.3982x over previous
#include <cuda_runtime.h>
#include <cuda_fp16.h>

// Problem constants
#define NK 3
#define NB 8
#define NT 1024
#define ND 1024
#define NR 32
#define ROWS_K (NB * NT)          // 8192 rows per area
#define ROWS_ALL (NK * ROWS_K)    // 24576 rows total
#define YN ((size_t)ROWS_ALL * ND) // output elems for y

// ---------------- scratch (device globals; no allocation allowed) -------------
__device__ float g_amp[24 * 8 * 1024];
__device__ float g_am[24 * 1024];
__device__ float g_pm[NB * NK * ND];
__device__ float g_h0[NB * NK * ND];
__device__ float g_h1[NB * 2 * ND];
__device__ float g_alpha[NB * NK];
__device__ float g_low[(size_t)ROWS_ALL * NR];

// packed fp16 hi/lo planes (u32 = pair of adjacent elements along k/d)
__device__ unsigned g_XH[(size_t)ROWS_ALL * 512];
__device__ unsigned g_XL[(size_t)ROWS_ALL * 512];
__device__ unsigned g_rH[(size_t)ROWS_K * 512];
__device__ unsigned g_rL[(size_t)ROWS_K * 512];
__device__ unsigned g_bcH[(size_t)ROWS_ALL * 512];
__device__ unsigned g_bcL[(size_t)ROWS_ALL * 512];
__device__ unsigned g_ahH[(size_t)ROWS_ALL * 512];
__device__ unsigned g_ahL[(size_t)ROWS_ALL * 512];
// weights packed per k-pair: [kp][1024]
__device__ unsigned g_WbH[1536 * 1024], g_WbL[1536 * 1024];
__device__ unsigned g_WaH[1536 * 1024], g_WaL[1536 * 1024];
__device__ unsigned g_Wm1H[1536 * 1024], g_Wm1L[1536 * 1024];
__device__ unsigned g_Wm2H[1536 * 1024], g_Wm2L[1536 * 1024];
__device__ unsigned g_WgH[3072 * 1024], g_WgL[3072 * 1024];

__device__ float g_gate[(size_t)ROWS_ALL * ND];
__device__ float g_m[(size_t)ROWS_ALL * ND];

// ---------------- helpers -----------------------------------------------------
__device__ __forceinline__ float gelu_f(float x) {
    return 0.5f * x * (1.0f + erff(x * 0.7071067811865476f));
}
__device__ __forceinline__ float sigm_f(float x) {
    return 1.0f / (1.0f + expf(-x));
}

// split two floats into packed-fp16 hi and lo words (element0 in low 16 bits)
__device__ __forceinline__ void split2(float x, float y, unsigned &hi, unsigned &lo) {
    __half hx = __float2half_rn(x);
    __half hy = __float2half_rn(y);
    float rx = x - __half2float(hx);
    float ry = y - __half2float(hy);
    __half lx = __float2half_rn(rx);
    __half ly = __float2half_rn(ry);
    hi = (unsigned)__half_as_ushort(hx) | ((unsigned)__half_as_ushort(hy) << 16);
    lo = (unsigned)__half_as_ushort(lx) | ((unsigned)__half_as_ushort(ly) << 16);
}

__device__ __forceinline__ float2 join2(unsigned h, unsigned l) {
    float x = __half2float(__ushort_as_half((unsigned short)(h & 0xffff)))
            + __half2float(__ushort_as_half((unsigned short)(l & 0xffff)));
    float y = __half2float(__ushort_as_half((unsigned short)(h >> 16)))
            + __half2float(__ushort_as_half((unsigned short)(l >> 16)));
    return make_float2(x, y);
}

__device__ __forceinline__ void mma16816(float* c, const unsigned* a, unsigned b0, unsigned b1) {
    asm volatile(
        "mma.sync.aligned.m16n8k16.row.col.f32.f16.f16.f32 "
        "{%0,%1,%2,%3}, {%4,%5,%6,%7}, {%8,%9}, {%0,%1,%2,%3};"
        : "+f"(c[0]), "+f"(c[1]), "+f"(c[2]), "+f"(c[3])
        : "r"(a[0]), "r"(a[1]), "r"(a[2]), "r"(a[3]), "r"(b0), "r"(b1));
}

__device__ __forceinline__ void ldsm_x4(unsigned &r0, unsigned &r1, unsigned &r2, unsigned &r3,
                                        unsigned saddr) {
    asm volatile("ldmatrix.sync.aligned.m8n8.x4.shared.b16 {%0,%1,%2,%3}, [%4];"
                 : "=r"(r0), "=r"(r1), "=r"(r2), "=r"(r3) : "r"(saddr));
}

#define CP16(dst, src) asm volatile("cp.async.ca.shared.global [%0], [%1], 16;" :: "r"(dst), "l"(src) : "memory")
#define CP_COMMIT() asm volatile("cp.async.commit_group;" ::: "memory")
#define CP_WAIT0() asm volatile("cp.async.wait_group 0;" ::: "memory")

__device__ __forceinline__ float2 blockReduce2(float a, float b) {
    __shared__ float sa[8], sb[8];
    int lane = threadIdx.x & 31;
    int w = threadIdx.x >> 5;
#pragma unroll
    for (int o = 16; o > 0; o >>= 1) {
        a += __shfl_xor_sync(0xffffffffu, a, o);
        b += __shfl_xor_sync(0xffffffffu, b, o);
    }
    if (lane == 0) { sa[w] = a; sb[w] = b; }
    __syncthreads();
    if (w == 0) {
        a = (lane < 8) ? sa[lane] : 0.f;
        b = (lane < 8) ? sb[lane] : 0.f;
#pragma unroll
        for (int o = 4; o > 0; o >>= 1) {
            a += __shfl_xor_sync(0xffffffffu, a, o);
            b += __shfl_xor_sync(0xffffffffu, b, o);
        }
        if (lane == 0) { sa[0] = a; sb[0] = b; }
    }
    __syncthreads();
    return make_float2(sa[0], sb[0]);
}

// ---------------- pre-split kernels -------------------------------------------
__global__ void __launch_bounds__(256) kSplitX(const float* __restrict__ src,
                                               unsigned* __restrict__ hi,
                                               unsigned* __restrict__ lo) {
    size_t q = (size_t)blockIdx.x * 256 + threadIdx.x;
    float4 v = *(const float4*)(src + q * 4);
    unsigned h0, l0, h1, l1;
    split2(v.x, v.y, h0, l0);
    split2(v.z, v.w, h1, l1);
    *(uint2*)(hi + q * 2) = make_uint2(h0, h1);
    *(uint2*)(lo + q * 2) = make_uint2(l0, l1);
}

__global__ void __launch_bounds__(256) kSplitW(const float* __restrict__ src,
                                               unsigned* __restrict__ hi,
                                               unsigned* __restrict__ lo) {
    size_t q = (size_t)blockIdx.x * 256 + threadIdx.x;
    size_t kp = q >> 8;
    size_t n4 = (q & 255) * 4;
    float4 e = *(const float4*)(src + (kp * 2) * 1024 + n4);
    float4 o = *(const float4*)(src + (kp * 2 + 1) * 1024 + n4);
    unsigned h[4], l[4];
    split2(e.x, o.x, h[0], l[0]);
    split2(e.y, o.y, h[1], l[1]);
    split2(e.z, o.z, h[2], l[2]);
    split2(e.w, o.w, h[3], l[3]);
    *(uint4*)(hi + kp * 1024 + n4) = make_uint4(h[0], h[1], h[2], h[3]);
    *(uint4*)(lo + kp * 1024 + n4) = make_uint4(l[0], l[1], l[2], l[3]);
}

// ---------------- controller --------------------------------------------------
__global__ void __launch_bounds__(256) kMeans(const float* __restrict__ X) {
    int slab = blockIdx.x;
    int chunk = blockIdx.y;
    size_t base = (size_t)slab * (NT * ND) + (size_t)chunk * 128 * ND;
    int col = threadIdx.x * 4;
    float4 acc = make_float4(0.f, 0.f, 0.f, 0.f);
#pragma unroll 4
    for (int t = 0; t < 128; t++) {
        float4 v = *(const float4*)(X + base + (size_t)t * ND + col);
        acc.x += v.x; acc.y += v.y; acc.z += v.z; acc.w += v.w;
    }
    *(float4*)&g_amp[(size_t)slab * 8192 + (size_t)chunk * 1024 + col] = acc;
}

__global__ void __launch_bounds__(256) kAm() {
    int bid = blockIdx.x;
    int b = bid / 3, k = bid % 3;
    int slab = k * 8 + b;
    for (int i = threadIdx.x; i < 1024; i += 256) {
        float acc = 0.f;
#pragma unroll
        for (int c = 0; c < 8; c++) acc += g_amp[(size_t)slab * 8192 + c * 1024 + i];
        g_am[bid * 1024 + i] = acc * (1.0f / 1024.0f);
    }
}

__global__ void __launch_bounds__(256) kPm2(const float* __restrict__ W,
                                            const float* __restrict__ bvec) {
    int col = blockIdx.x * 64 + (threadIdx.x & 63);
    int rg = threadIdx.x >> 6;
    float acc[6];
#pragma unroll
    for (int j = 0; j < 6; j++) acc[j] = 0.f;
    for (int dd = 0; dd < 1024; dd++) {
        float w = W[(size_t)dd * 1024 + col];
#pragma unroll
        for (int j = 0; j < 6; j++)
            acc[j] += g_am[(rg * 6 + j) * 1024 + dd] * w;
    }
    float bias = bvec[col];
#pragma unroll
    for (int j = 0; j < 6; j++)
        g_pm[(size_t)(rg * 6 + j) * 1024 + col] = gelu_f(acc[j] + bias);
}

__global__ void __launch_bounds__(256) kLN1(const float* __restrict__ gvec,
                                            const float* __restrict__ bvec) {
    int b = blockIdx.x;
    size_t base = (size_t)b * 3072;
    int i0 = threadIdx.x * 4;
    float4 v[3];
    float s = 0.f, sq = 0.f;
#pragma unroll
    for (int c = 0; c < 3; c++) {
        v[c] = *(const float4*)&g_pm[base + c * 1024 + i0];
        s += v[c].x + v[c].y + v[c].z + v[c].w;
        sq += v[c].x * v[c].x + v[c].y * v[c].y + v[c].z * v[c].z + v[c].w * v[c].w;
    }
    float2 r = blockReduce2(s, sq);
    float mu = r.x * (1.0f / 3072.0f);
    float var = r.y * (1.0f / 3072.0f) - mu * mu;
    float rstd = rsqrtf(var + 1e-5f);
#pragma unroll
    for (int c = 0; c < 3; c++) {
        int idx = c * 1024 + i0;
        float4 G = *(const float4*)(gvec + idx);
        float4 Bv = *(const float4*)(bvec + idx);
        float4 o;
        o.x = (v[c].x - mu) * rstd * G.x + Bv.x;
        o.y = (v[c].y - mu) * rstd * G.y + Bv.y;
        o.z = (v[c].z - mu) * rstd * G.z + Bv.z;
        o.w = (v[c].w - mu) * rstd * G.w + Bv.w;
        *(float4*)&g_h0[base + idx] = o;
    }
}

__global__ void __launch_bounds__(256) kH1(const float* __restrict__ W1,
                                           const float* __restrict__ b1) {
    int col = blockIdx.x * 64 + (threadIdx.x & 63);
    int bq = threadIdx.x >> 6;
    float a0 = 0.f, a1 = 0.f;
    const float* h0a = g_h0 + (size_t)bq * 3072;
    const float* h0b = g_h0 + (size_t)(bq + 4) * 3072;
    for (int dd = 0; dd < 3072; dd++) {
        float w = W1[(size_t)dd * 2048 + col];
        a0 += h0a[dd] * w;
        a1 += h0b[dd] * w;
    }
    float bias = b1[col];
    g_h1[(size_t)bq * 2048 + col] = gelu_f(a0 + bias);
    g_h1[(size_t)(bq + 4) * 2048 + col] = gelu_f(a1 + bias);
}

__global__ void __launch_bounds__(256) kLogits(const float* __restrict__ W2,
                                               const float* __restrict__ b2,
                                               const float* __restrict__ gum,
                                               float* __restrict__ outLog) {
    __shared__ float s0[256], s1[256], s2[256];
    int b = blockIdx.x;
    int tid = threadIdx.x;
    float a0 = 0.f, a1 = 0.f, a2 = 0.f;
    for (int dd = tid; dd < 2048; dd += 256) {
        float v = g_h1[(size_t)b * 2048 + dd];
        a0 += v * W2[dd * 3 + 0];
        a1 += v * W2[dd * 3 + 1];
        a2 += v * W2[dd * 3 + 2];
    }
    s0[tid] = a0; s1[tid] = a1; s2[tid] = a2;
    __syncthreads();
    for (int off = 128; off > 0; off >>= 1) {
        if (tid < off) { s0[tid] += s0[tid + off]; s1[tid] += s1[tid + off]; s2[tid] += s2[tid + off]; }
        __syncthreads();
    }
    if (tid == 0) {
        float lg[3];
        lg[0] = s0[0] + b2[0]; lg[1] = s1[0] + b2[1]; lg[2] = s2[0] + b2[2];
        float z[3];
#pragma unroll
        for (int j = 0; j < 3; j++) {
            outLog[b * 3 + j] = lg[j];
            z[j] = (lg[j] + gum[b * 3 + j]) * 1.25f;
        }
        float m = fmaxf(z[0], fmaxf(z[1], z[2]));
        float e0 = expf(z[0] - m), e1 = expf(z[1] - m), e2 = expf(z[2] - m);
        float inv = 1.0f / (e0 + e1 + e2);
        g_alpha[b * 3 + 0] = e0 * inv;
        g_alpha[b * 3 + 1] = e1 * inv;
        g_alpha[b * 3 + 2] = e2 * inv;
    }
}

// ---------------- router ------------------------------------------------------
__global__ void __launch_bounds__(256) kLow(const float* __restrict__ X,
                                            const float* __restrict__ V) {
    __shared__ float Xs[64][33];
    __shared__ float Vs[32][32];
    int row0 = blockIdx.x * 64;
    int k = row0 >> 13;
    int tid = threadIdx.x;
    int tx = tid & 31, ty = tid >> 5;
    float acc[8];
#pragma unroll
    for (int i = 0; i < 8; i++) acc[i] = 0.f;

    for (int d0 = 0; d0 < 1024; d0 += 32) {
#pragma unroll
        for (int i = 0; i < 8; i++) {
            int idx = tid + i * 256;
            int r = idx >> 5, c = idx & 31;
            Xs[r][c] = X[(size_t)(row0 + r) * ND + d0 + c];
        }
#pragma unroll
        for (int i = 0; i < 4; i++) {
            int idx = tid + i * 256;
            int dd = idx >> 5, rr = idx & 31;
            Vs[dd][rr] = V[((size_t)k * 1024 + d0 + dd) * 32 + rr];
        }
        __syncthreads();
#pragma unroll
        for (int dd = 0; dd < 32; dd++) {
            float vv = Vs[dd][tx];
#pragma unroll
            for (int rr = 0; rr < 8; rr++) acc[rr] += Xs[rr * 8 + ty][dd] * vv;
        }
        __syncthreads();
    }
#pragma unroll
    for (int rr = 0; rr < 8; rr++)
        g_low[(size_t)(row0 + rr * 8 + ty) * 32 + tx] = acc[rr];
}

__global__ void __launch_bounds__(256) kRouted(const float* __restrict__ U) {
    __shared__ float As[96][64];
    __shared__ float Us[96][64];
    int col0 = blockIdx.x * 64;
    int row0 = blockIdx.y * 64;
    int tid = threadIdx.x;
    int tx = tid & 15, ty = tid >> 4;

    for (int idx = tid; idx < 6144; idx += 256) {
        int r0 = idx / 96, p = idx - r0 * 96;
        int k = p >> 5, rr = p & 31;
        int row = row0 + r0;
        int b = row >> 10;
        As[p][r0] = g_alpha[b * 3 + k] * g_low[((size_t)k * 8192 + row) * 32 + rr];
    }
    for (int idx = tid; idx < 6144; idx += 256) {
        int p = idx >> 6, e = idx & 63;
        int k = p >> 5, rr = p & 31;
        Us[p][e] = U[((size_t)k * 1024 + col0 + e) * 32 + rr];
    }
    __syncthreads();

    float acc[4][4];
#pragma unroll
    for (int i = 0; i < 4; i++)
#pragma unroll
        for (int j = 0; j < 4; j++) acc[i][j] = 0.f;

#pragma unroll 8
    for (int p = 0; p < 96; p++) {
        float4 u4 = *(const float4*)&Us[p][tx * 4];
        float a0 = As[p][ty * 4 + 0], a1 = As[p][ty * 4 + 1];
        float a2 = As[p][ty * 4 + 2], a3 = As[p][ty * 4 + 3];
        acc[0][0] += a0 * u4.x; acc[0][1] += a0 * u4.y; acc[0][2] += a0 * u4.z; acc[0][3] += a0 * u4.w;
        acc[1][0] += a1 * u4.x; acc[1][1] += a1 * u4.y; acc[1][2] += a1 * u4.z; acc[1][3] += a1 * u4.w;
        acc[2][0] += a2 * u4.x; acc[2][1] += a2 * u4.y; acc[2][2] += a2 * u4.z; acc[2][3] += a2 * u4.w;
        acc[3][0] += a3 * u4.x; acc[3][1] += a3 * u4.y; acc[3][2] += a3 * u4.z; acc[3][3] += a3 * u4.w;
    }
#pragma unroll
    for (int i = 0; i < 4; i++) {
        unsigned h0, l0, h1, l1;
        split2(acc[i][0], acc[i][1], h0, l0);
        split2(acc[i][2], acc[i][3], h1, l1);
        size_t base = (size_t)(row0 + ty * 4 + i) * 512 + ((col0 + tx * 4) >> 1);
        *(uint2*)&g_rH[base] = make_uint2(h0, h1);
        *(uint2*)&g_rL[base] = make_uint2(l0, l1);
    }
}

// ===== tensor-core GEMM: fp16 2-term (Ahi*Bhi + Ahi*Blo), cp.async + ldmatrix ==
// mode: 0=store fp32, 1=gelu fp32, 2=sigmoid(prev+v+bias) fp32,
//       3=prev*gelu(v) fp32, 4=gelu -> packed hi/lo planes
// csel: 0=bcomp(packed), 1=ah(packed), 2=gate(fp32), 3=m(fp32)
__global__ void __launch_bounds__(256) gemm_tc(
    const unsigned* __restrict__ hiA, const unsigned* __restrict__ loA, size_t aZ,
    const unsigned* __restrict__ hiW, const unsigned* __restrict__ loW,
    size_t wOffKp, size_t wZKp,
    const float* __restrict__ bias, int csel, int mode)
{
    (void)loA;
    const int z = blockIdx.z;
    const int row0 = blockIdx.y * 128;
    const int col0 = blockIdx.x * 128;

    const unsigned* Ah_g = hiA + (size_t)z * aZ + (size_t)row0 * 512;
    const size_t wBase = ((size_t)z * wZKp + wOffKp) * 1024 + col0;

    // A: row-major [row][12] (8 used kp + 4 pad -> ldmatrix conflict-free)
    __shared__ unsigned Ah[2][128][12];
    __shared__ unsigned Bh[2][8][132], Bl[2][8][132];

    const int tid = threadIdx.x;
    const int lane = tid & 31;
    const int wid = tid >> 5;
    const int wm = wid & 1;
    const int wn = wid >> 1;
    const int qrow = lane >> 2;
    const int qk = lane & 3;

    // fill mapping
    const int fr = tid >> 1;            // A row 0..127
    const int fq = tid & 1;             // A 16B-chunk (kp 0-3 / 4-7)
    const int bkp = tid >> 5;           // B kp 0..7
    const int bn4 = (tid & 31) * 4;     // B n offset

    const unsigned sAh = (unsigned)__cvta_generic_to_shared(&Ah[0][0][0]);
    const unsigned sBh = (unsigned)__cvta_generic_to_shared(&Bh[0][0][0]);
    const unsigned sBl = (unsigned)__cvta_generic_to_shared(&Bl[0][0][0]);
    const unsigned A_BUF = 128 * 12 * 4;   // bytes per A buffer
    const unsigned B_BUF = 8 * 132 * 4;

    const unsigned daOff = (unsigned)(fr * 48 + fq * 16);
    const unsigned dbOff = (unsigned)(bkp * 132 * 4 + bn4 * 4);

    float acc[4][4][4];
#pragma unroll
    for (int i = 0; i < 4; i++)
#pragma unroll
        for (int j = 0; j < 4; j++)
#pragma unroll
            for (int q = 0; q < 4; q++) acc[i][j][q] = 0.f;

    // prologue: issue stage 0 into buffer 0
    {
        CP16(sAh + daOff, Ah_g + (size_t)fr * 512 + fq * 4);
        CP16(sBh + dbOff, &hiW[wBase + (size_t)bkp * 1024 + bn4]);
        CP16(sBl + dbOff, &loW[wBase + (size_t)bkp * 1024 + bn4]);
        CP_COMMIT();
    }

    // ldmatrix lane address components (A): row = mb + (lane&15), khalf = lane>>4
    const unsigned lrow = (unsigned)(lane & 15);
    const unsigned lkh = (unsigned)((lane >> 4) * 16);   // byte offset for k-half

#pragma unroll 1
    for (int kt = 0; kt < 64; kt++) {
        const int cur = kt & 1;
        CP_WAIT0();
        __syncthreads();

        // issue next stage into the other buffer (overlaps compute)
        if (kt < 63) {
            const int nb = cur ^ 1;
            size_t kpo = (size_t)(kt + 1) * 8;
            CP16(sAh + nb * A_BUF + daOff, Ah_g + (size_t)fr * 512 + kpo + fq * 4);
            CP16(sBh + nb * B_BUF + dbOff, &hiW[wBase + (kpo + bkp) * 1024 + bn4]);
            CP16(sBl + nb * B_BUF + dbOff, &loW[wBase + (kpo + bkp) * 1024 + bn4]);
            CP_COMMIT();
        }

        // B fragments (hi + lo)
        unsigned fBh[4][2], fBl[4][2];
#pragma unroll
        for (int nt = 0; nt < 4; nt++) {
            int nbx = wn * 32 + nt * 8 + qrow;
            fBh[nt][0] = Bh[cur][qk][nbx]; fBh[nt][1] = Bh[cur][qk + 4][nbx];
            fBl[nt][0] = Bl[cur][qk][nbx]; fBl[nt][1] = Bl[cur][qk + 4][nbx];
        }

        // A hi fragments via ldmatrix + 8 mma per mt
#pragma unroll
        for (int mt = 0; mt < 4; mt++) {
            unsigned mb = (unsigned)(wm * 64 + mt * 16);
            unsigned rowAddr = (mb + lrow) * 48 + lkh;
            unsigned fAh[4];
            ldsm_x4(fAh[0], fAh[1], fAh[2], fAh[3], sAh + cur * A_BUF + rowAddr);
#pragma unroll
            for (int nt = 0; nt < 4; nt++) {
                mma16816(acc[mt][nt], fAh, fBh[nt][0], fBh[nt][1]);
                mma16816(acc[mt][nt], fAh, fBl[nt][0], fBl[nt][1]);
            }
        }
    }

    // ---------------- fused epilogue ----------------
    if (mode == 4) {
        unsigned* cH = (csel == 0 ? g_bcH : g_ahH) + ((size_t)z * ROWS_K + row0) * 512 + (col0 >> 1);
        unsigned* cL = (csel == 0 ? g_bcL : g_ahL) + ((size_t)z * ROWS_K + row0) * 512 + (col0 >> 1);
#pragma unroll
        for (int mt = 0; mt < 4; mt++) {
            int rbase = wm * 64 + mt * 16 + qrow;
#pragma unroll
            for (int half = 0; half < 2; half++) {
                int r = rbase + half * 8;
#pragma unroll
                for (int nt = 0; nt < 4; nt++) {
                    int c = wn * 32 + nt * 8 + 2 * qk;
                    float v0 = gelu_f(acc[mt][nt][half * 2 + 0]);
                    float v1 = gelu_f(acc[mt][nt][half * 2 + 1]);
                    unsigned h, l;
                    split2(v0, v1, h, l);
                    cH[(size_t)r * 512 + (c >> 1)] = h;
                    cL[(size_t)r * 512 + (c >> 1)] = l;
                }
            }
        }
    } else {
        float* Cb = (csel == 2 ? g_gate : g_m) + (size_t)z * ROWS_K * ND + (size_t)row0 * ND + col0;
#pragma unroll
        for (int mt = 0; mt < 4; mt++) {
            int rbase = wm * 64 + mt * 16 + qrow;
#pragma unroll
            for (int half = 0; half < 2; half++) {
                int r = rbase + half * 8;
#pragma unroll
                for (int nt = 0; nt < 4; nt++) {
                    int c = wn * 32 + nt * 8 + 2 * qk;
                    float v0 = acc[mt][nt][half * 2 + 0];
                    float v1 = acc[mt][nt][half * 2 + 1];
                    float* cp = Cb + (size_t)r * ND + c;
                    if (mode == 0) {
                        *(float2*)cp = make_float2(v0, v1);
                    } else if (mode == 1) {
                        *(float2*)cp = make_float2(gelu_f(v0), gelu_f(v1));
                    } else if (mode == 2) {
                        float2 p = *(float2*)cp;
                        float b0 = bias[(size_t)z * ND + col0 + c];
                        float b1 = bias[(size_t)z * ND + col0 + c + 1];
                        *(float2*)cp = make_float2(sigm_f(p.x + v0 + b0), sigm_f(p.y + v1 + b1));
                    } else {
                        float2 p = *(float2*)cp;
                        *(float2*)cp = make_float2(p.x * gelu_f(v0), p.y * gelu_f(v1));
                    }
                }
            }
        }
    }
}

// ---------------- final: y = LN(x + (1-g)*b + g*m) * lng + lnb ----------------
__global__ void __launch_bounds__(256) kFinal(const float* __restrict__ X,
                                              const float* __restrict__ cg,
                                              const float* __restrict__ cb,
                                              float* __restrict__ out) {
    size_t row = blockIdx.x;
    int k = (int)(row >> 13);
    size_t base = row * ND + threadIdx.x * 4;
    size_t pbase = row * 512 + threadIdx.x * 2;
    float4 x  = *(const float4*)(X + base);
    uint2 bh = *(const uint2*)(g_bcH + pbase);
    uint2 bl = *(const uint2*)(g_bcL + pbase);
    float2 b01 = join2(bh.x, bl.x);
    float2 b23 = join2(bh.y, bl.y);
    float4 gv = *(const float4*)(g_gate + base);
    float4 mv = *(const float4*)(g_m + base);
    float4 v;
    v.x = x.x + (1.f - gv.x) * b01.x + gv.x * mv.x;
    v.y = x.y + (1.f - gv.y) * b01.y + gv.y * mv.y;
    v.z = x.z + (1.f - gv.z) * b23.x + gv.z * mv.z;
    v.w = x.w + (1.f - gv.w) * b23.y + gv.w * mv.w;
    float s = v.x + v.y + v.z + v.w;
    float sq = v.x * v.x + v.y * v.y + v.z * v.z + v.w * v.w;
    float2 r = blockReduce2(s, sq);
    float mu = r.x * (1.0f / 1024.0f);
    float var = r.y * (1.0f / 1024.0f) - mu * mu;
    float rstd = rsqrtf(var + 1e-5f);
    int ci = k * 1024 + threadIdx.x * 4;
    float4 G = *(const float4*)(cg + ci);
    float4 Bv = *(const float4*)(cb + ci);
    float4 o;
    o.x = (v.x - mu) * rstd * G.x + Bv.x;
    o.y = (v.y - mu) * rstd * G.y + Bv.y;
    o.z = (v.z - mu) * rstd * G.z + Bv.z;
    o.w = (v.w - mu) * rstd * G.w + Bv.w;
    *(float4*)(out + base) = o;
}

// ---------------- launch ------------------------------------------------------
extern "C" void kernel_launch(void* const* d_in, const int* in_sizes, int n_in,
                              void* d_out, int out_size) {
    (void)in_sizes; (void)n_in; (void)out_size;
    const float* X    = (const float*)d_in[0];
    const float* gum  = (const float*)d_in[1];
    const float* prW  = (const float*)d_in[2];
    const float* prB  = (const float*)d_in[3];
    const float* hlg  = (const float*)d_in[4];
    const float* hlb  = (const float*)d_in[5];
    const float* W1   = (const float*)d_in[6];
    const float* b1   = (const float*)d_in[7];
    const float* W2   = (const float*)d_in[8];
    const float* b2   = (const float*)d_in[9];
    const float* U    = (const float*)d_in[10];
    const float* V    = (const float*)d_in[11];
    const float* Wb   = (const float*)d_in[12];
    const float* Wa   = (const float*)d_in[13];
    const float* Wg   = (const float*)d_in[14];
    const float* bg   = (const float*)d_in[15];
    const float* Wm1  = (const float*)d_in[16];
    const float* Wm2  = (const float*)d_in[17];
    const float* clg  = (const float*)d_in[18];
    const float* clb  = (const float*)d_in[19];
    float* out = (float*)d_out;

    unsigned *xh, *xl, *wbh, *wbl, *wah, *wal, *wgh, *wgl, *wm1h, *wm1l, *wm2h, *wm2l;
    unsigned *rh, *rl, *bch, *bcl, *ahh, *ahl;
    cudaGetSymbolAddress((void**)&xh, g_XH);   cudaGetSymbolAddress((void**)&xl, g_XL);
    cudaGetSymbolAddress((void**)&wbh, g_WbH); cudaGetSymbolAddress((void**)&wbl, g_WbL);
    cudaGetSymbolAddress((void**)&wah, g_WaH); cudaGetSymbolAddress((void**)&wal, g_WaL);
    cudaGetSymbolAddress((void**)&wgh, g_WgH); cudaGetSymbolAddress((void**)&wgl, g_WgL);
    cudaGetSymbolAddress((void**)&wm1h, g_Wm1H); cudaGetSymbolAddress((void**)&wm1l, g_Wm1L);
    cudaGetSymbolAddress((void**)&wm2h, g_Wm2H); cudaGetSymbolAddress((void**)&wm2l, g_Wm2L);
    cudaGetSymbolAddress((void**)&rh, g_rH);   cudaGetSymbolAddress((void**)&rl, g_rL);
    cudaGetSymbolAddress((void**)&bch, g_bcH); cudaGetSymbolAddress((void**)&bcl, g_bcL);
    cudaGetSymbolAddress((void**)&ahh, g_ahH); cudaGetSymbolAddress((void**)&ahl, g_ahL);

    const size_t AZ = (size_t)ROWS_K * 512;
    dim3 gg(8, 64, 3);

    // splits first; X-only GEMMs early (6th launch = gemm_tc for ncu capture)
    kSplitX<<<24576, 256>>>(X, xh, xl);
    kSplitW<<<1536, 256>>>(Wb, wbh, wbl);
    kSplitW<<<3072, 256>>>(Wg, wgh, wgl);
    kSplitW<<<1536, 256>>>(Wm1, wm1h, wm1l);
    kSplitW<<<1536, 256>>>(Wm2, wm2h, wm2l);
    gemm_tc<<<gg, 256>>>(xh, xl, AZ, wbh, wbl, 0, 512, nullptr, 0, 4);   // bcomp = gelu(X@Wb) -> packed
    gemm_tc<<<gg, 256>>>(xh, xl, AZ, wgh, wgl, 0, 1024, nullptr, 2, 0);  // gate = X@Wg_top (raw)
    kSplitW<<<1536, 256>>>(Wa, wah, wal);

    // controller
    kMeans<<<dim3(24, 8), 256>>>(X);
    kAm<<<24, 256>>>();
    kPm2<<<16, 256>>>(prW, prB);
    kLN1<<<8, 256>>>(hlg, hlb);
    kH1<<<32, 256>>>(W1, b1);
    kLogits<<<8, 256>>>(W2, b2, gum, out + YN);

    // router
    kLow<<<ROWS_ALL / 64, 256>>>(X, V);
    kRouted<<<dim3(16, 128), 256>>>(U);

    // routed-dependent + second pass GEMMs
    gemm_tc<<<gg, 256>>>(rh, rl, 0,  wah, wal, 0, 512, nullptr, 1, 4);    // ah = gelu(routed@Wa) -> packed
    gemm_tc<<<gg, 256>>>(rh, rl, 0,  wgh, wgl, 512, 1024, bg, 2, 2);      // gate = sigmoid(.+routed@Wg_bot+bg)
    gemm_tc<<<gg, 256>>>(bch, bcl, AZ, wm1h, wm1l, 0, 512, nullptr, 3, 1); // m = gelu(bcomp@Wm1)
    gemm_tc<<<gg, 256>>>(ahh, ahl, AZ, wm2h, wm2l, 0, 512, nullptr, 3, 3); // m *= gelu(ah@Wm2)

    // final LN + output
    kFinal<<<ROWS_ALL, 256>>>(X, clg, clb, out);
}

// round 15
// speedup vs baseline: 1.6693x; 1.1939x over previous
#include <cuda_runtime.h>
#include <cuda_fp16.h>

// Problem constants
#define NK 3
#define NB 8
#define NT 1024
#define ND 1024
#define NR 32
#define ROWS_K (NB * NT)          // 8192 rows per area
#define ROWS_ALL (NK * ROWS_K)    // 24576 rows total
#define YN ((size_t)ROWS_ALL * ND) // output elems for y

// ---------------- scratch (device globals; no allocation allowed) -------------
__device__ float g_amp[24 * 8 * 1024];
__device__ float g_am[24 * 1024];
__device__ float g_pm[NB * NK * ND];
__device__ float g_h0[NB * NK * ND];
__device__ float g_h1[NB * 2 * ND];
__device__ float g_alpha[NB * NK];
__device__ float g_low[(size_t)ROWS_ALL * NR];

// packed fp16 hi/lo planes (u32 = pair of adjacent elements along k/d)
__device__ unsigned g_XH[(size_t)ROWS_ALL * 512];
__device__ unsigned g_rH[(size_t)ROWS_K * 512];
__device__ unsigned g_bcH[(size_t)ROWS_ALL * 512];
__device__ unsigned g_bcL[(size_t)ROWS_ALL * 512];
__device__ unsigned g_ahH[(size_t)ROWS_ALL * 512];
__device__ unsigned g_ahL[(size_t)ROWS_ALL * 512];
// weights packed per k-pair: [kp][1024] (hi plane only)
__device__ unsigned g_WbH[1536 * 1024];
__device__ unsigned g_WaH[1536 * 1024];
__device__ unsigned g_Wm1H[1536 * 1024];
__device__ unsigned g_Wm2H[1536 * 1024];
__device__ unsigned g_WgH[3072 * 1024];

__device__ float g_gate[(size_t)ROWS_ALL * ND];
__device__ float g_m[(size_t)ROWS_ALL * ND];

// ---------------- helpers -----------------------------------------------------
__device__ __forceinline__ float gelu_f(float x) {
    return 0.5f * x * (1.0f + erff(x * 0.7071067811865476f));
}
__device__ __forceinline__ float sigm_f(float x) {
    return 1.0f / (1.0f + expf(-x));
}

// pack two floats into fp16x2 (element0 in low 16 bits)
__device__ __forceinline__ unsigned pack2(float x, float y) {
    __half hx = __float2half_rn(x);
    __half hy = __float2half_rn(y);
    return (unsigned)__half_as_ushort(hx) | ((unsigned)__half_as_ushort(hy) << 16);
}

// split two floats into packed-fp16 hi and lo words
__device__ __forceinline__ void split2(float x, float y, unsigned &hi, unsigned &lo) {
    __half hx = __float2half_rn(x);
    __half hy = __float2half_rn(y);
    float rx = x - __half2float(hx);
    float ry = y - __half2float(hy);
    __half lx = __float2half_rn(rx);
    __half ly = __float2half_rn(ry);
    hi = (unsigned)__half_as_ushort(hx) | ((unsigned)__half_as_ushort(hy) << 16);
    lo = (unsigned)__half_as_ushort(lx) | ((unsigned)__half_as_ushort(ly) << 16);
}

__device__ __forceinline__ float2 join2(unsigned h, unsigned l) {
    float x = __half2float(__ushort_as_half((unsigned short)(h & 0xffff)))
            + __half2float(__ushort_as_half((unsigned short)(l & 0xffff)));
    float y = __half2float(__ushort_as_half((unsigned short)(h >> 16)))
            + __half2float(__ushort_as_half((unsigned short)(l >> 16)));
    return make_float2(x, y);
}

__device__ __forceinline__ void mma16816(float* c, const unsigned* a, unsigned b0, unsigned b1) {
    asm volatile(
        "mma.sync.aligned.m16n8k16.row.col.f32.f16.f16.f32 "
        "{%0,%1,%2,%3}, {%4,%5,%6,%7}, {%8,%9}, {%0,%1,%2,%3};"
        : "+f"(c[0]), "+f"(c[1]), "+f"(c[2]), "+f"(c[3])
        : "r"(a[0]), "r"(a[1]), "r"(a[2]), "r"(a[3]), "r"(b0), "r"(b1));
}

__device__ __forceinline__ void ldsm_x4(unsigned &r0, unsigned &r1, unsigned &r2, unsigned &r3,
                                        unsigned saddr) {
    asm volatile("ldmatrix.sync.aligned.m8n8.x4.shared.b16 {%0,%1,%2,%3}, [%4];"
                 : "=r"(r0), "=r"(r1), "=r"(r2), "=r"(r3) : "r"(saddr));
}

#define CP16(dst, src) asm volatile("cp.async.ca.shared.global [%0], [%1], 16;" :: "r"(dst), "l"(src) : "memory")
#define CP_COMMIT() asm volatile("cp.async.commit_group;" ::: "memory")
#define CP_WAIT0() asm volatile("cp.async.wait_group 0;" ::: "memory")

__device__ __forceinline__ float2 blockReduce2(float a, float b) {
    __shared__ float sa[8], sb[8];
    int lane = threadIdx.x & 31;
    int w = threadIdx.x >> 5;
#pragma unroll
    for (int o = 16; o > 0; o >>= 1) {
        a += __shfl_xor_sync(0xffffffffu, a, o);
        b += __shfl_xor_sync(0xffffffffu, b, o);
    }
    if (lane == 0) { sa[w] = a; sb[w] = b; }
    __syncthreads();
    if (w == 0) {
        a = (lane < 8) ? sa[lane] : 0.f;
        b = (lane < 8) ? sb[lane] : 0.f;
#pragma unroll
        for (int o = 4; o > 0; o >>= 1) {
            a += __shfl_xor_sync(0xffffffffu, a, o);
            b += __shfl_xor_sync(0xffffffffu, b, o);
        }
        if (lane == 0) { sa[0] = a; sb[0] = b; }
    }
    __syncthreads();
    return make_float2(sa[0], sb[0]);
}

// ---------------- pre-split kernels (hi plane only) ----------------------------
__global__ void __launch_bounds__(256) kSplitX(const float* __restrict__ src,
                                               unsigned* __restrict__ hi) {
    size_t q = (size_t)blockIdx.x * 256 + threadIdx.x;
    float4 v = *(const float4*)(src + q * 4);
    *(uint2*)(hi + q * 2) = make_uint2(pack2(v.x, v.y), pack2(v.z, v.w));
}

__global__ void __launch_bounds__(256) kSplitW(const float* __restrict__ src,
                                               unsigned* __restrict__ hi) {
    size_t q = (size_t)blockIdx.x * 256 + threadIdx.x;
    size_t kp = q >> 8;
    size_t n4 = (q & 255) * 4;
    float4 e = *(const float4*)(src + (kp * 2) * 1024 + n4);
    float4 o = *(const float4*)(src + (kp * 2 + 1) * 1024 + n4);
    *(uint4*)(hi + kp * 1024 + n4) = make_uint4(
        pack2(e.x, o.x), pack2(e.y, o.y), pack2(e.z, o.z), pack2(e.w, o.w));
}

// ---------------- controller --------------------------------------------------
__global__ void __launch_bounds__(256) kMeans(const float* __restrict__ X) {
    int slab = blockIdx.x;
    int chunk = blockIdx.y;
    size_t base = (size_t)slab * (NT * ND) + (size_t)chunk * 128 * ND;
    int col = threadIdx.x * 4;
    float4 acc = make_float4(0.f, 0.f, 0.f, 0.f);
#pragma unroll 4
    for (int t = 0; t < 128; t++) {
        float4 v = *(const float4*)(X + base + (size_t)t * ND + col);
        acc.x += v.x; acc.y += v.y; acc.z += v.z; acc.w += v.w;
    }
    *(float4*)&g_amp[(size_t)slab * 8192 + (size_t)chunk * 1024 + col] = acc;
}

__global__ void __launch_bounds__(256) kAm() {
    int bid = blockIdx.x;
    int b = bid / 3, k = bid % 3;
    int slab = k * 8 + b;
    for (int i = threadIdx.x; i < 1024; i += 256) {
        float acc = 0.f;
#pragma unroll
        for (int c = 0; c < 8; c++) acc += g_amp[(size_t)slab * 8192 + c * 1024 + i];
        g_am[bid * 1024 + i] = acc * (1.0f / 1024.0f);
    }
}

__global__ void __launch_bounds__(256) kPm2(const float* __restrict__ W,
                                            const float* __restrict__ bvec) {
    int col = blockIdx.x * 64 + (threadIdx.x & 63);
    int rg = threadIdx.x >> 6;
    float acc[6];
#pragma unroll
    for (int j = 0; j < 6; j++) acc[j] = 0.f;
    for (int dd = 0; dd < 1024; dd++) {
        float w = W[(size_t)dd * 1024 + col];
#pragma unroll
        for (int j = 0; j < 6; j++)
            acc[j] += g_am[(rg * 6 + j) * 1024 + dd] * w;
    }
    float bias = bvec[col];
#pragma unroll
    for (int j = 0; j < 6; j++)
        g_pm[(size_t)(rg * 6 + j) * 1024 + col] = gelu_f(acc[j] + bias);
}

__global__ void __launch_bounds__(256) kLN1(const float* __restrict__ gvec,
                                            const float* __restrict__ bvec) {
    int b = blockIdx.x;
    size_t base = (size_t)b * 3072;
    int i0 = threadIdx.x * 4;
    float4 v[3];
    float s = 0.f, sq = 0.f;
#pragma unroll
    for (int c = 0; c < 3; c++) {
        v[c] = *(const float4*)&g_pm[base + c * 1024 + i0];
        s += v[c].x + v[c].y + v[c].z + v[c].w;
        sq += v[c].x * v[c].x + v[c].y * v[c].y + v[c].z * v[c].z + v[c].w * v[c].w;
    }
    float2 r = blockReduce2(s, sq);
    float mu = r.x * (1.0f / 3072.0f);
    float var = r.y * (1.0f / 3072.0f) - mu * mu;
    float rstd = rsqrtf(var + 1e-5f);
#pragma unroll
    for (int c = 0; c < 3; c++) {
        int idx = c * 1024 + i0;
        float4 G = *(const float4*)(gvec + idx);
        float4 Bv = *(const float4*)(bvec + idx);
        float4 o;
        o.x = (v[c].x - mu) * rstd * G.x + Bv.x;
        o.y = (v[c].y - mu) * rstd * G.y + Bv.y;
        o.z = (v[c].z - mu) * rstd * G.z + Bv.z;
        o.w = (v[c].w - mu) * rstd * G.w + Bv.w;
        *(float4*)&g_h0[base + idx] = o;
    }
}

__global__ void __launch_bounds__(256) kH1(const float* __restrict__ W1,
                                           const float* __restrict__ b1) {
    int col = blockIdx.x * 64 + (threadIdx.x & 63);
    int bq = threadIdx.x >> 6;
    float a0 = 0.f, a1 = 0.f;
    const float* h0a = g_h0 + (size_t)bq * 3072;
    const float* h0b = g_h0 + (size_t)(bq + 4) * 3072;
    for (int dd = 0; dd < 3072; dd++) {
        float w = W1[(size_t)dd * 2048 + col];
        a0 += h0a[dd] * w;
        a1 += h0b[dd] * w;
    }
    float bias = b1[col];
    g_h1[(size_t)bq * 2048 + col] = gelu_f(a0 + bias);
    g_h1[(size_t)(bq + 4) * 2048 + col] = gelu_f(a1 + bias);
}

__global__ void __launch_bounds__(256) kLogits(const float* __restrict__ W2,
                                               const float* __restrict__ b2,
                                               const float* __restrict__ gum,
                                               float* __restrict__ outLog) {
    __shared__ float s0[256], s1[256], s2[256];
    int b = blockIdx.x;
    int tid = threadIdx.x;
    float a0 = 0.f, a1 = 0.f, a2 = 0.f;
    for (int dd = tid; dd < 2048; dd += 256) {
        float v = g_h1[(size_t)b * 2048 + dd];
        a0 += v * W2[dd * 3 + 0];
        a1 += v * W2[dd * 3 + 1];
        a2 += v * W2[dd * 3 + 2];
    }
    s0[tid] = a0; s1[tid] = a1; s2[tid] = a2;
    __syncthreads();
    for (int off = 128; off > 0; off >>= 1) {
        if (tid < off) { s0[tid] += s0[tid + off]; s1[tid] += s1[tid + off]; s2[tid] += s2[tid + off]; }
        __syncthreads();
    }
    if (tid == 0) {
        float lg[3];
        lg[0] = s0[0] + b2[0]; lg[1] = s1[0] + b2[1]; lg[2] = s2[0] + b2[2];
        float z[3];
#pragma unroll
        for (int j = 0; j < 3; j++) {
            outLog[b * 3 + j] = lg[j];
            z[j] = (lg[j] + gum[b * 3 + j]) * 1.25f;
        }
        float m = fmaxf(z[0], fmaxf(z[1], z[2]));
        float e0 = expf(z[0] - m), e1 = expf(z[1] - m), e2 = expf(z[2] - m);
        float inv = 1.0f / (e0 + e1 + e2);
        g_alpha[b * 3 + 0] = e0 * inv;
        g_alpha[b * 3 + 1] = e1 * inv;
        g_alpha[b * 3 + 2] = e2 * inv;
    }
}

// ---------------- router ------------------------------------------------------
__global__ void __launch_bounds__(256) kLow(const float* __restrict__ X,
                                            const float* __restrict__ V) {
    __shared__ float Xs[64][33];
    __shared__ float Vs[32][32];
    int row0 = blockIdx.x * 64;
    int k = row0 >> 13;
    int tid = threadIdx.x;
    int tx = tid & 31, ty = tid >> 5;
    float acc[8];
#pragma unroll
    for (int i = 0; i < 8; i++) acc[i] = 0.f;

    for (int d0 = 0; d0 < 1024; d0 += 32) {
#pragma unroll
        for (int i = 0; i < 8; i++) {
            int idx = tid + i * 256;
            int r = idx >> 5, c = idx & 31;
            Xs[r][c] = X[(size_t)(row0 + r) * ND + d0 + c];
        }
#pragma unroll
        for (int i = 0; i < 4; i++) {
            int idx = tid + i * 256;
            int dd = idx >> 5, rr = idx & 31;
            Vs[dd][rr] = V[((size_t)k * 1024 + d0 + dd) * 32 + rr];
        }
        __syncthreads();
#pragma unroll
        for (int dd = 0; dd < 32; dd++) {
            float vv = Vs[dd][tx];
#pragma unroll
            for (int rr = 0; rr < 8; rr++) acc[rr] += Xs[rr * 8 + ty][dd] * vv;
        }
        __syncthreads();
    }
#pragma unroll
    for (int rr = 0; rr < 8; rr++)
        g_low[(size_t)(row0 + rr * 8 + ty) * 32 + tx] = acc[rr];
}

__global__ void __launch_bounds__(256) kRouted(const float* __restrict__ U) {
    __shared__ float As[96][64];
    __shared__ float Us[96][64];
    int col0 = blockIdx.x * 64;
    int row0 = blockIdx.y * 64;
    int tid = threadIdx.x;
    int tx = tid & 15, ty = tid >> 4;

    for (int idx = tid; idx < 6144; idx += 256) {
        int r0 = idx / 96, p = idx - r0 * 96;
        int k = p >> 5, rr = p & 31;
        int row = row0 + r0;
        int b = row >> 10;
        As[p][r0] = g_alpha[b * 3 + k] * g_low[((size_t)k * 8192 + row) * 32 + rr];
    }
    for (int idx = tid; idx < 6144; idx += 256) {
        int p = idx >> 6, e = idx & 63;
        int k = p >> 5, rr = p & 31;
        Us[p][e] = U[((size_t)k * 1024 + col0 + e) * 32 + rr];
    }
    __syncthreads();

    float acc[4][4];
#pragma unroll
    for (int i = 0; i < 4; i++)
#pragma unroll
        for (int j = 0; j < 4; j++) acc[i][j] = 0.f;

#pragma unroll 8
    for (int p = 0; p < 96; p++) {
        float4 u4 = *(const float4*)&Us[p][tx * 4];
        float a0 = As[p][ty * 4 + 0], a1 = As[p][ty * 4 + 1];
        float a2 = As[p][ty * 4 + 2], a3 = As[p][ty * 4 + 3];
        acc[0][0] += a0 * u4.x; acc[0][1] += a0 * u4.y; acc[0][2] += a0 * u4.z; acc[0][3] += a0 * u4.w;
        acc[1][0] += a1 * u4.x; acc[1][1] += a1 * u4.y; acc[1][2] += a1 * u4.z; acc[1][3] += a1 * u4.w;
        acc[2][0] += a2 * u4.x; acc[2][1] += a2 * u4.y; acc[2][2] += a2 * u4.z; acc[2][3] += a2 * u4.w;
        acc[3][0] += a3 * u4.x; acc[3][1] += a3 * u4.y; acc[3][2] += a3 * u4.z; acc[3][3] += a3 * u4.w;
    }
#pragma unroll
    for (int i = 0; i < 4; i++) {
        size_t base = (size_t)(row0 + ty * 4 + i) * 512 + ((col0 + tx * 4) >> 1);
        *(uint2*)&g_rH[base] = make_uint2(pack2(acc[i][0], acc[i][1]),
                                          pack2(acc[i][2], acc[i][3]));
    }
}

// ===== tensor-core GEMM: pure fp16 (1 MMA/product), cp.async + ldmatrix ========
// mode: 0=store fp32, 1=gelu fp32, 2=sigmoid(prev+v+bias) fp32,
//       3=prev*gelu(v) fp32, 4=gelu -> packed hi/lo planes
// csel: 0=bcomp(packed), 1=ah(packed), 2=gate(fp32), 3=m(fp32)
__global__ void __launch_bounds__(256) gemm_tc(
    const unsigned* __restrict__ hiA, size_t aZ,
    const unsigned* __restrict__ hiW,
    size_t wOffKp, size_t wZKp,
    const float* __restrict__ bias, int csel, int mode)
{
    const int z = blockIdx.z;
    const int row0 = blockIdx.y * 128;
    const int col0 = blockIdx.x * 128;

    const unsigned* Ah_g = hiA + (size_t)z * aZ + (size_t)row0 * 512;
    const size_t wBase = ((size_t)z * wZKp + wOffKp) * 1024 + col0;

    // A: row-major [row][12] (8 used kp + 4 pad -> ldmatrix conflict-free)
    __shared__ unsigned Ah[2][128][12];
    __shared__ unsigned Bh[2][8][132];

    const int tid = threadIdx.x;
    const int lane = tid & 31;
    const int wid = tid >> 5;
    const int wm = wid & 1;
    const int wn = wid >> 1;
    const int qrow = lane >> 2;
    const int qk = lane & 3;

    // fill mapping
    const int fr = tid >> 1;            // A row 0..127
    const int fq = tid & 1;             // A 16B-chunk (kp 0-3 / 4-7)
    const int bkp = tid >> 5;           // B kp 0..7
    const int bn4 = (tid & 31) * 4;     // B n offset

    const unsigned sAh = (unsigned)__cvta_generic_to_shared(&Ah[0][0][0]);
    const unsigned sBh = (unsigned)__cvta_generic_to_shared(&Bh[0][0][0]);
    const unsigned A_BUF = 128 * 12 * 4;   // bytes per A buffer
    const unsigned B_BUF = 8 * 132 * 4;

    const unsigned daOff = (unsigned)(fr * 48 + fq * 16);
    const unsigned dbOff = (unsigned)(bkp * 132 * 4 + bn4 * 4);

    float acc[4][4][4];
#pragma unroll
    for (int i = 0; i < 4; i++)
#pragma unroll
        for (int j = 0; j < 4; j++)
#pragma unroll
            for (int q = 0; q < 4; q++) acc[i][j][q] = 0.f;

    // prologue: issue stage 0 into buffer 0
    {
        CP16(sAh + daOff, Ah_g + (size_t)fr * 512 + fq * 4);
        CP16(sBh + dbOff, &hiW[wBase + (size_t)bkp * 1024 + bn4]);
        CP_COMMIT();
    }

    // ldmatrix lane address components (A): row = mb + (lane&15), khalf = lane>>4
    const unsigned lrow = (unsigned)(lane & 15);
    const unsigned lkh = (unsigned)((lane >> 4) * 16);   // byte offset for k-half

#pragma unroll 1
    for (int kt = 0; kt < 64; kt++) {
        const int cur = kt & 1;
        CP_WAIT0();
        __syncthreads();

        // issue next stage into the other buffer (overlaps compute)
        if (kt < 63) {
            const int nb = cur ^ 1;
            size_t kpo = (size_t)(kt + 1) * 8;
            CP16(sAh + nb * A_BUF + daOff, Ah_g + (size_t)fr * 512 + kpo + fq * 4);
            CP16(sBh + nb * B_BUF + dbOff, &hiW[wBase + (kpo + bkp) * 1024 + bn4]);
            CP_COMMIT();
        }

        // B fragments
        unsigned fBh[4][2];
#pragma unroll
        for (int nt = 0; nt < 4; nt++) {
            int nbx = wn * 32 + nt * 8 + qrow;
            fBh[nt][0] = Bh[cur][qk][nbx]; fBh[nt][1] = Bh[cur][qk + 4][nbx];
        }

        // A fragments via ldmatrix + 4 mma per mt
#pragma unroll
        for (int mt = 0; mt < 4; mt++) {
            unsigned mb = (unsigned)(wm * 64 + mt * 16);
            unsigned rowAddr = (mb + lrow) * 48 + lkh;
            unsigned fAh[4];
            ldsm_x4(fAh[0], fAh[1], fAh[2], fAh[3], sAh + cur * A_BUF + rowAddr);
#pragma unroll
            for (int nt = 0; nt < 4; nt++) {
                mma16816(acc[mt][nt], fAh, fBh[nt][0], fBh[nt][1]);
            }
        }
    }

    // ---------------- fused epilogue ----------------
    if (mode == 4) {
        unsigned* cH = (csel == 0 ? g_bcH : g_ahH) + ((size_t)z * ROWS_K + row0) * 512 + (col0 >> 1);
        unsigned* cL = (csel == 0 ? g_bcL : g_ahL) + ((size_t)z * ROWS_K + row0) * 512 + (col0 >> 1);
#pragma unroll
        for (int mt = 0; mt < 4; mt++) {
            int rbase = wm * 64 + mt * 16 + qrow;
#pragma unroll
            for (int half = 0; half < 2; half++) {
                int r = rbase + half * 8;
#pragma unroll
                for (int nt = 0; nt < 4; nt++) {
                    int c = wn * 32 + nt * 8 + 2 * qk;
                    float v0 = gelu_f(acc[mt][nt][half * 2 + 0]);
                    float v1 = gelu_f(acc[mt][nt][half * 2 + 1]);
                    unsigned h, l;
                    split2(v0, v1, h, l);
                    cH[(size_t)r * 512 + (c >> 1)] = h;
                    cL[(size_t)r * 512 + (c >> 1)] = l;
                }
            }
        }
    } else {
        float* Cb = (csel == 2 ? g_gate : g_m) + (size_t)z * ROWS_K * ND + (size_t)row0 * ND + col0;
#pragma unroll
        for (int mt = 0; mt < 4; mt++) {
            int rbase = wm * 64 + mt * 16 + qrow;
#pragma unroll
            for (int half = 0; half < 2; half++) {
                int r = rbase + half * 8;
#pragma unroll
                for (int nt = 0; nt < 4; nt++) {
                    int c = wn * 32 + nt * 8 + 2 * qk;
                    float v0 = acc[mt][nt][half * 2 + 0];
                    float v1 = acc[mt][nt][half * 2 + 1];
                    float* cp = Cb + (size_t)r * ND + c;
                    if (mode == 0) {
                        *(float2*)cp = make_float2(v0, v1);
                    } else if (mode == 1) {
                        *(float2*)cp = make_float2(gelu_f(v0), gelu_f(v1));
                    } else if (mode == 2) {
                        float2 p = *(float2*)cp;
                        float b0 = bias[(size_t)z * ND + col0 + c];
                        float b1 = bias[(size_t)z * ND + col0 + c + 1];
                        *(float2*)cp = make_float2(sigm_f(p.x + v0 + b0), sigm_f(p.y + v1 + b1));
                    } else {
                        float2 p = *(float2*)cp;
                        *(float2*)cp = make_float2(p.x * gelu_f(v0), p.y * gelu_f(v1));
                    }
                }
            }
        }
    }
}

// ---------------- final: y = LN(x + (1-g)*b + g*m) * lng + lnb ----------------
__global__ void __launch_bounds__(256) kFinal(const float* __restrict__ X,
                                              const float* __restrict__ cg,
                                              const float* __restrict__ cb,
                                              float* __restrict__ out) {
    size_t row = blockIdx.x;
    int k = (int)(row >> 13);
    size_t base = row * ND + threadIdx.x * 4;
    size_t pbase = row * 512 + threadIdx.x * 2;
    float4 x  = *(const float4*)(X + base);
    uint2 bh = *(const uint2*)(g_bcH + pbase);
    uint2 bl = *(const uint2*)(g_bcL + pbase);
    float2 b01 = join2(bh.x, bl.x);
    float2 b23 = join2(bh.y, bl.y);
    float4 gv = *(const float4*)(g_gate + base);
    float4 mv = *(const float4*)(g_m + base);
    float4 v;
    v.x = x.x + (1.f - gv.x) * b01.x + gv.x * mv.x;
    v.y = x.y + (1.f - gv.y) * b01.y + gv.y * mv.y;
    v.z = x.z + (1.f - gv.z) * b23.x + gv.z * mv.z;
    v.w = x.w + (1.f - gv.w) * b23.y + gv.w * mv.w;
    float s = v.x + v.y + v.z + v.w;
    float sq = v.x * v.x + v.y * v.y + v.z * v.z + v.w * v.w;
    float2 r = blockReduce2(s, sq);
    float mu = r.x * (1.0f / 1024.0f);
    float var = r.y * (1.0f / 1024.0f) - mu * mu;
    float rstd = rsqrtf(var + 1e-5f);
    int ci = k * 1024 + threadIdx.x * 4;
    float4 G = *(const float4*)(cg + ci);
    float4 Bv = *(const float4*)(cb + ci);
    float4 o;
    o.x = (v.x - mu) * rstd * G.x + Bv.x;
    o.y = (v.y - mu) * rstd * G.y + Bv.y;
    o.z = (v.z - mu) * rstd * G.z + Bv.z;
    o.w = (v.w - mu) * rstd * G.w + Bv.w;
    *(float4*)(out + base) = o;
}

// ---------------- launch ------------------------------------------------------
extern "C" void kernel_launch(void* const* d_in, const int* in_sizes, int n_in,
                              void* d_out, int out_size) {
    (void)in_sizes; (void)n_in; (void)out_size;
    const float* X    = (const float*)d_in[0];
    const float* gum  = (const float*)d_in[1];
    const float* prW  = (const float*)d_in[2];
    const float* prB  = (const float*)d_in[3];
    const float* hlg  = (const float*)d_in[4];
    const float* hlb  = (const float*)d_in[5];
    const float* W1   = (const float*)d_in[6];
    const float* b1   = (const float*)d_in[7];
    const float* W2   = (const float*)d_in[8];
    const float* b2   = (const float*)d_in[9];
    const float* U    = (const float*)d_in[10];
    const float* V    = (const float*)d_in[11];
    const float* Wb   = (const float*)d_in[12];
    const float* Wa   = (const float*)d_in[13];
    const float* Wg   = (const float*)d_in[14];
    const float* bg   = (const float*)d_in[15];
    const float* Wm1  = (const float*)d_in[16];
    const float* Wm2  = (const float*)d_in[17];
    const float* clg  = (const float*)d_in[18];
    const float* clb  = (const float*)d_in[19];
    float* out = (float*)d_out;

    unsigned *xh, *wbh, *wah, *wgh, *wm1h, *wm2h;
    unsigned *rh, *bch, *ahh;
    cudaGetSymbolAddress((void**)&xh, g_XH);
    cudaGetSymbolAddress((void**)&wbh, g_WbH);
    cudaGetSymbolAddress((void**)&wah, g_WaH);
    cudaGetSymbolAddress((void**)&wgh, g_WgH);
    cudaGetSymbolAddress((void**)&wm1h, g_Wm1H);
    cudaGetSymbolAddress((void**)&wm2h, g_Wm2H);
    cudaGetSymbolAddress((void**)&rh, g_rH);
    cudaGetSymbolAddress((void**)&bch, g_bcH);
    cudaGetSymbolAddress((void**)&ahh, g_ahH);

    const size_t AZ = (size_t)ROWS_K * 512;
    dim3 gg(8, 64, 3);

    // splits first; X-only GEMMs early (6th launch = gemm_tc for ncu capture)
    kSplitX<<<24576, 256>>>(X, xh);
    kSplitW<<<1536, 256>>>(Wb, wbh);
    kSplitW<<<3072, 256>>>(Wg, wgh);
    kSplitW<<<1536, 256>>>(Wm1, wm1h);
    kSplitW<<<1536, 256>>>(Wm2, wm2h);
    gemm_tc<<<gg, 256>>>(xh, AZ, wbh, 0, 512, nullptr, 0, 4);   // bcomp = gelu(X@Wb) -> packed
    gemm_tc<<<gg, 256>>>(xh, AZ, wgh, 0, 1024, nullptr, 2, 0);  // gate = X@Wg_top (raw)
    kSplitW<<<1536, 256>>>(Wa, wah);

    // controller
    kMeans<<<dim3(24, 8), 256>>>(X);
    kAm<<<24, 256>>>();
    kPm2<<<16, 256>>>(prW, prB);
    kLN1<<<8, 256>>>(hlg, hlb);
    kH1<<<32, 256>>>(W1, b1);
    kLogits<<<8, 256>>>(W2, b2, gum, out + YN);

    // router
    kLow<<<ROWS_ALL / 64, 256>>>(X, V);
    kRouted<<<dim3(16, 128), 256>>>(U);

    // routed-dependent + second pass GEMMs
    gemm_tc<<<gg, 256>>>(rh, 0,  wah, 0, 512, nullptr, 1, 4);    // ah = gelu(routed@Wa) -> packed
    gemm_tc<<<gg, 256>>>(rh, 0,  wgh, 512, 1024, bg, 2, 2);      // gate = sigmoid(.+routed@Wg_bot+bg)
    gemm_tc<<<gg, 256>>>(bch, AZ, wm1h, 0, 512, nullptr, 3, 1);  // m = gelu(bcomp@Wm1)
    gemm_tc<<<gg, 256>>>(ahh, AZ, wm2h, 0, 512, nullptr, 3, 3);  // m *= gelu(ah@Wm2)

    // final LN + output
    kFinal<<<ROWS_ALL, 256>>>(X, clg, clb, out);
}